// round 8
// baseline (speedup 1.0000x reference)
#include <cuda_runtime.h>
#include <cuda_fp16.h>
#include <cstdint>

// Problem dims
#define GM 512      // batch
#define GK 4096     // IN
#define GN 11008    // OUT

// Tiling: BM=256, BN=64, BK=64, split-K by 4, 2 CTAs/SM
#define BM      256
#define BN      64
#define BK      64
#define KSPLIT  4
#define KRANGE  (GK / KSPLIT)     // 1024
#define NK      (KRANGE / BK)     // 16 k-tiles per CTA
#define THREADS 256
#define PAD     8
#define LDS_K   (BK + PAD)        // 72 halves -> 144B rows, ldmatrix conflict-free

// fp16 x scratch (allocation-free rule: __device__ global)
__device__ __half g_x[(size_t)GM * GK];   // 4MB, L2-resident

// ---------------------------------------------------------------------------
__device__ __forceinline__ uint32_t smem_u32(const void* p) {
    return (uint32_t)__cvta_generic_to_shared(p);
}
__device__ __forceinline__ void cp_async16(void* smem, const void* gmem) {
    asm volatile("cp.async.cg.shared.global [%0], [%1], 16;\n"
                 ::"r"(smem_u32(smem)), "l"(gmem));
}

// ---------------------------------------------------------------------------
__global__ void k_convert_x(const float* __restrict__ x) {
    const int n4 = GM * GK / 4;
    uint2* xo = (uint2*)g_x;
    const float4* xi = (const float4*)x;
    for (int i = blockIdx.x * blockDim.x + threadIdx.x; i < n4;
         i += gridDim.x * blockDim.x) {
        float4 v = xi[i];
        __half2 a = __floats2half2_rn(v.x, v.y);
        __half2 b = __floats2half2_rn(v.z, v.w);
        uint2 o;
        o.x = *(unsigned int*)&a;
        o.y = *(unsigned int*)&b;
        xo[i] = o;
    }
}

// out[b][o] = bias[o]  (split-K partials red.add on top)
__global__ void k_init_out(const float* __restrict__ bias, float* __restrict__ out) {
    const int n4 = GM * GN / 4;
    const int gn4 = GN / 4;
    float4* o4 = (float4*)out;
    const float4* b4 = (const float4*)bias;
    for (int i = blockIdx.x * blockDim.x + threadIdx.x; i < n4;
         i += gridDim.x * blockDim.x) {
        o4[i] = b4[i % gn4];
    }
}

// out *= scale[o]
__global__ void k_finalize(const float* __restrict__ scale, float* __restrict__ out) {
    const int n4 = GM * GN / 4;
    const int gn4 = GN / 4;
    float4* o4 = (float4*)out;
    const float4* s4 = (const float4*)scale;
    for (int i = blockIdx.x * blockDim.x + threadIdx.x; i < n4;
         i += gridDim.x * blockDim.x) {
        float4 v = o4[i];
        float4 s = s4[i % gn4];
        v.x *= s.x; v.y *= s.y; v.z *= s.z; v.w *= s.w;
        o4[i] = v;
    }
}

// ---------------------------------------------------------------------------
// Fused GEMM: grid (172 n-tiles, 2 m-tiles, 4 k-splits), 256 threads, occ 2.
// 8 warps = 4(m) x 2(n), warp tile 64x32. W decompressed inline per k-tile.
// Inner accumulation in f16 (chained over the 4 K=16 mmas of one k-tile),
// promoted to persistent f32 accumulators once per k-tile.
// ---------------------------------------------------------------------------
#define SMEM_DYN (2 * (BM * LDS_K + BN * LDS_K) * 2)   // 92160 B

__global__ void __launch_bounds__(THREADS, 2)
k_fused(const int* __restrict__ stored, const int* __restrict__ sign,
        const float* __restrict__ lmin_p, const float* __restrict__ lmax_p,
        float* __restrict__ out) {
    extern __shared__ __half dynsmem[];
    __shared__ unsigned short lut[256];

    __half* As[2]  = {dynsmem, dynsmem + BM * LDS_K};
    __half* Wsm[2] = {dynsmem + 2 * BM * LDS_K, dynsmem + 2 * BM * LDS_K + BN * LDS_K};

    const int tid = threadIdx.x;
    const int lane = tid & 31;
    const int warp = tid >> 5;
    const int wm = warp >> 1;   // 0..3 over M
    const int wn = warp & 1;    // 0..1 over N
    const int n0 = blockIdx.x * BN;
    const int m0base = blockIdx.y * BM;
    const int kbase = blockIdx.z * KRANGE;

    {
        float lmin = *lmin_p;
        float lrange = *lmax_p - lmin;
        for (int i = tid; i < 256; i += THREADS) {
            float lw = lmin + ((255.0f - (float)i) * (1.0f / 254.0f)) * lrange;
            lut[i] = __half_as_ushort(__float2half_rn(__expf(lw)));
        }
    }
    __syncthreads();

    float acc[4][4][4];
#pragma unroll
    for (int a = 0; a < 4; a++)
#pragma unroll
        for (int b = 0; b < 4; b++)
#pragma unroll
            for (int c = 0; c < 4; c++) acc[a][b][c] = 0.f;

    // X: 2048 16B-chunks per stage (256 rows x 8), 8 per thread
    auto load_x = [&](int st, int kt) {
        const int kk = kbase + kt * BK;
#pragma unroll
        for (int j = 0; j < 8; ++j) {
            int t = tid + j * THREADS;
            int row = t >> 3;              // 0..255
            int cx = t & 7;
            cp_async16(As[st] + row * LDS_K + cx * 8,
                       g_x + (size_t)(m0base + row) * GK + kk + cx * 8);
        }
    };

    // W: 512 16B-chunks per stage (64 rows x 8), 2 per thread; inline decompress
    auto decomp_w = [&](int st, int kt) {
#pragma unroll
        for (int j = 0; j < 2; ++j) {
            int c = tid + j * THREADS;     // 0..511
            int row = c >> 3;              // 0..63
            int cx = c & 7;
            const size_t goff = (size_t)(n0 + row) * GK + kbase + kt * BK + cx * 8;
            int4 sa = ((const int4*)(stored + goff))[0];
            int4 sb = ((const int4*)(stored + goff))[1];
            int4 ga = ((const int4*)(sign + goff))[0];
            int4 gb = ((const int4*)(sign + goff))[1];
            unsigned int h0 = lut[sa.x] ^ ((((unsigned)ga.x) >> 16) & 0x8000u);
            unsigned int h1 = lut[sa.y] ^ ((((unsigned)ga.y) >> 16) & 0x8000u);
            unsigned int h2 = lut[sa.z] ^ ((((unsigned)ga.z) >> 16) & 0x8000u);
            unsigned int h3 = lut[sa.w] ^ ((((unsigned)ga.w) >> 16) & 0x8000u);
            unsigned int h4 = lut[sb.x] ^ ((((unsigned)gb.x) >> 16) & 0x8000u);
            unsigned int h5 = lut[sb.y] ^ ((((unsigned)gb.y) >> 16) & 0x8000u);
            unsigned int h6 = lut[sb.z] ^ ((((unsigned)gb.z) >> 16) & 0x8000u);
            unsigned int h7 = lut[sb.w] ^ ((((unsigned)gb.w) >> 16) & 0x8000u);
            uint4 o;
            o.x = h0 | (h1 << 16);
            o.y = h2 | (h3 << 16);
            o.z = h4 | (h5 << 16);
            o.w = h6 | (h7 << 16);
            *(uint4*)(Wsm[st] + row * LDS_K + cx * 8) = o;
        }
    };

    // prologue
    load_x(0, 0);
    asm volatile("cp.async.commit_group;\n" ::: "memory");
    decomp_w(0, 0);
    load_x(1, 1);
    asm volatile("cp.async.commit_group;\n" ::: "memory");

    const int arow = lane & 15;
    const int acol = (lane >> 4) * 8;

    for (int kt = 0; kt < NK; ++kt) {
        const int s = kt & 1;
        asm volatile("cp.async.wait_group 1;\n" ::: "memory");
        __syncthreads();   // stage s ready (X cp.async + W STS from prev iter)

        // decompress next W into stage s^1 (no race: s^1 readers from kt-1 are
        // past the barrier above; kt+1 readers wait at the next barrier)
        if (kt + 1 < NK) decomp_w(s ^ 1, kt + 1);

        // f16 accumulators for this k-tile (chained across the 4 ks steps)
        unsigned int hacc[4][4][2];
#pragma unroll
        for (int mi = 0; mi < 4; ++mi)
#pragma unroll
            for (int nf = 0; nf < 4; ++nf) {
                hacc[mi][nf][0] = 0u;
                hacc[mi][nf][1] = 0u;
            }

#pragma unroll
        for (int ks = 0; ks < BK / 16; ++ks) {
            unsigned int afr[4][4];
            unsigned int bfr[4][2];
#pragma unroll
            for (int mi = 0; mi < 4; ++mi) {
                unsigned int addr = smem_u32(
                    As[s] + (wm * 64 + mi * 16 + arow) * LDS_K + ks * 16 + acol);
                asm volatile(
                    "ldmatrix.sync.aligned.m8n8.x4.shared.b16 {%0,%1,%2,%3}, [%4];\n"
                    : "=r"(afr[mi][0]), "=r"(afr[mi][1]), "=r"(afr[mi][2]),
                      "=r"(afr[mi][3])
                    : "r"(addr));
            }
#pragma unroll
            for (int nj = 0; nj < 2; ++nj) {
                unsigned int q0, q1, q2, q3;
                unsigned int addr = smem_u32(
                    Wsm[s] + (wn * 32 + nj * 16 + arow) * LDS_K + ks * 16 + acol);
                asm volatile(
                    "ldmatrix.sync.aligned.m8n8.x4.shared.b16 {%0,%1,%2,%3}, [%4];\n"
                    : "=r"(q0), "=r"(q1), "=r"(q2), "=r"(q3)
                    : "r"(addr));
                bfr[nj * 2][0] = q0;
                bfr[nj * 2][1] = q2;
                bfr[nj * 2 + 1][0] = q1;
                bfr[nj * 2 + 1][1] = q3;
            }
#pragma unroll
            for (int mi = 0; mi < 4; ++mi)
#pragma unroll
                for (int nf = 0; nf < 4; ++nf) {
                    asm volatile(
                        "mma.sync.aligned.m16n8k16.row.col.f16.f16.f16.f16 "
                        "{%0,%1}, {%2,%3,%4,%5}, {%6,%7}, {%0,%1};\n"
                        : "+r"(hacc[mi][nf][0]), "+r"(hacc[mi][nf][1])
                        : "r"(afr[mi][0]), "r"(afr[mi][1]), "r"(afr[mi][2]),
                          "r"(afr[mi][3]), "r"(bfr[nf][0]), "r"(bfr[nf][1]));
                }
        }

        // promote this k-tile's f16 partials into the f32 accumulators
#pragma unroll
        for (int mi = 0; mi < 4; ++mi)
#pragma unroll
            for (int nf = 0; nf < 4; ++nf) {
                float2 f0 = __half22float2(*(__half2*)&hacc[mi][nf][0]);
                float2 f1 = __half22float2(*(__half2*)&hacc[mi][nf][1]);
                acc[mi][nf][0] += f0.x;
                acc[mi][nf][1] += f0.y;
                acc[mi][nf][2] += f1.x;
                acc[mi][nf][3] += f1.y;
            }

        __syncthreads();   // stage-s readers done before X refill
        if (kt + 2 < NK) load_x(s, kt + 2);
        asm volatile("cp.async.commit_group;\n" ::: "memory");
    }

    // epilogue: red.add into out (pre-initialized with bias; atomics measured ~free)
    const int row = lane >> 2;
    const int col2 = (lane & 3) * 2;
#pragma unroll
    for (int mi = 0; mi < 4; ++mi) {
        int m0 = m0base + wm * 64 + mi * 16 + row;
#pragma unroll
        for (int nf = 0; nf < 4; ++nf) {
            int nn = n0 + wn * 32 + nf * 8 + col2;
            atomicAdd(&out[(size_t)m0 * GN + nn],           acc[mi][nf][0]);
            atomicAdd(&out[(size_t)m0 * GN + nn + 1],       acc[mi][nf][1]);
            atomicAdd(&out[(size_t)(m0 + 8) * GN + nn],     acc[mi][nf][2]);
            atomicAdd(&out[(size_t)(m0 + 8) * GN + nn + 1], acc[mi][nf][3]);
        }
    }
}

// ---------------------------------------------------------------------------
extern "C" void kernel_launch(void* const* d_in, const int* in_sizes, int n_in,
                              void* d_out, int out_size) {
    const float* x      = (const float*)d_in[0];
    const int*   stored = (const int*)d_in[1];
    const int*   sign   = (const int*)d_in[2];
    const float* lmin   = (const float*)d_in[3];
    const float* lmax   = (const float*)d_in[4];
    const float* scale  = (const float*)d_in[5];
    const float* bias   = (const float*)d_in[6];
    float* out = (float*)d_out;

    cudaFuncSetAttribute(k_fused, cudaFuncAttributeMaxDynamicSharedMemorySize, SMEM_DYN);

    k_convert_x<<<512, 256>>>(x);
    k_init_out<<<1024, 256>>>(bias, out);
    dim3 grid(GN / BN, GM / BM, KSPLIT);   // (172, 2, 4)
    k_fused<<<grid, THREADS, SMEM_DYN>>>(stored, sign, lmin, lmax, out);
    k_finalize<<<1024, 256>>>(scale, out);
}

// round 9
// speedup vs baseline: 1.2711x; 1.2711x over previous
#include <cuda_runtime.h>
#include <cuda_fp16.h>
#include <cstdint>

// Problem dims
#define GM 512      // batch
#define GK 4096     // IN
#define GN 11008    // OUT

// GEMM tiling: BM=128, BN=128, BK=64, 3-stage, split-K 2, occ 2
#define BM      128
#define BN      128
#define BK      64
#define KSPLIT  2
#define KRANGE  (GK / KSPLIT)     // 2048
#define NK      (KRANGE / BK)     // 32 k-tiles per CTA
#define THREADS 256
#define PAD     8
#define LDS_K   (BK + PAD)        // 72 halves -> 144B rows, ldmatrix conflict-free
#define STAGES  3

// Scratch (allocation-free rule: __device__ globals)
__device__ __half g_w[(size_t)GN * GK];   // 90MB decompressed fp16 W (L2-resident)
__device__ __half g_x[(size_t)GM * GK];   // 4MB fp16 x

// ---------------------------------------------------------------------------
__device__ __forceinline__ uint32_t smem_u32(const void* p) {
    return (uint32_t)__cvta_generic_to_shared(p);
}
__device__ __forceinline__ void cp_async16(void* smem, const void* gmem) {
    asm volatile("cp.async.cg.shared.global [%0], [%1], 16;\n"
                 ::"r"(smem_u32(smem)), "l"(gmem));
}

// ---------------------------------------------------------------------------
// QINS decompress: 256-entry LUT, sign via fp16 sign-bit XOR. At DRAM roofline.
// ---------------------------------------------------------------------------
__global__ void k_decompress(const int* __restrict__ stored,
                             const int* __restrict__ sign,
                             const float* __restrict__ lmin_p,
                             const float* __restrict__ lmax_p) {
    __shared__ unsigned short lut[256];
    float lmin = *lmin_p;
    float lrange = *lmax_p - lmin;
    for (int i = threadIdx.x; i < 256; i += blockDim.x) {
        float lw = lmin + ((255.0f - (float)i) * (1.0f / 254.0f)) * lrange;
        lut[i] = __half_as_ushort(__float2half_rn(__expf(lw)));
    }
    __syncthreads();

    const int4* s4 = (const int4*)stored;
    const int4* g4 = (const int4*)sign;
    uint4* w4 = (uint4*)g_w;

    const long long n8 = (long long)GN * GK / 8;
    long long i = (long long)blockIdx.x * blockDim.x + threadIdx.x;
    const long long stride = (long long)gridDim.x * blockDim.x;

    for (; i < n8; i += stride) {
        int4 sa = s4[2 * i], sb = s4[2 * i + 1];
        int4 ga = g4[2 * i], gb = g4[2 * i + 1];
        unsigned int h0 = lut[sa.x] ^ ((((unsigned)ga.x) >> 16) & 0x8000u);
        unsigned int h1 = lut[sa.y] ^ ((((unsigned)ga.y) >> 16) & 0x8000u);
        unsigned int h2 = lut[sa.z] ^ ((((unsigned)ga.z) >> 16) & 0x8000u);
        unsigned int h3 = lut[sa.w] ^ ((((unsigned)ga.w) >> 16) & 0x8000u);
        unsigned int h4 = lut[sb.x] ^ ((((unsigned)gb.x) >> 16) & 0x8000u);
        unsigned int h5 = lut[sb.y] ^ ((((unsigned)gb.y) >> 16) & 0x8000u);
        unsigned int h6 = lut[sb.z] ^ ((((unsigned)gb.z) >> 16) & 0x8000u);
        unsigned int h7 = lut[sb.w] ^ ((((unsigned)gb.w) >> 16) & 0x8000u);
        uint4 o;
        o.x = h0 | (h1 << 16);
        o.y = h2 | (h3 << 16);
        o.z = h4 | (h5 << 16);
        o.w = h6 | (h7 << 16);
        w4[i] = o;
    }
}

// ---------------------------------------------------------------------------
__global__ void k_convert_x(const float* __restrict__ x) {
    const int n4 = GM * GK / 4;
    uint2* xo = (uint2*)g_x;
    const float4* xi = (const float4*)x;
    for (int i = blockIdx.x * blockDim.x + threadIdx.x; i < n4;
         i += gridDim.x * blockDim.x) {
        float4 v = xi[i];
        __half2 a = __floats2half2_rn(v.x, v.y);
        __half2 b = __floats2half2_rn(v.z, v.w);
        uint2 o;
        o.x = *(unsigned int*)&a;
        o.y = *(unsigned int*)&b;
        xo[i] = o;
    }
}

// out[b][o] = bias[o]*scale[o]; split-K partials (scaled) red.add on top
__global__ void k_init_out(const float* __restrict__ bias,
                           const float* __restrict__ scale,
                           float* __restrict__ out) {
    const int n4 = GM * GN / 4;
    const int gn4 = GN / 4;
    float4* o4 = (float4*)out;
    const float4* b4 = (const float4*)bias;
    const float4* s4 = (const float4*)scale;
    for (int i = blockIdx.x * blockDim.x + threadIdx.x; i < n4;
         i += gridDim.x * blockDim.x) {
        int c = i % gn4;
        float4 b = b4[c];
        float4 s = s4[c];
        float4 r;
        r.x = b.x * s.x; r.y = b.y * s.y; r.z = b.z * s.z; r.w = b.w * s.w;
        o4[i] = r;
    }
}

// ---------------------------------------------------------------------------
// Clean GEMM: all operands via 3-stage cp.async from g_w/g_x (both L2-warm).
// Grid (86, 4, 2). 256 threads = 8 warps = 2(m) x 4(n), warp tile 64x32.
// Epilogue: atomicAdd(out, scale*acc).
// ---------------------------------------------------------------------------
#define SMEM_DYN (STAGES * (BM + BN) * LDS_K * 2)   // 110592 B

__global__ void __launch_bounds__(THREADS, 2)
k_gemm(const float* __restrict__ scale, float* __restrict__ out) {
    extern __shared__ __half dynsmem[];
    // stage st: A at dynsmem + st*(BM+BN)*LDS_K, W right after A
    const int tid = threadIdx.x;
    const int lane = tid & 31;
    const int warp = tid >> 5;
    const int wm = warp & 1;    // 0..1 over M
    const int wn = warp >> 1;   // 0..3 over N
    const int n0 = blockIdx.x * BN;
    const int m0 = blockIdx.y * BM;
    const int kbase = blockIdx.z * KRANGE;

    float acc[4][4][4];
#pragma unroll
    for (int a = 0; a < 4; a++)
#pragma unroll
        for (int b = 0; b < 4; b++)
#pragma unroll
            for (int c = 0; c < 4; c++) acc[a][b][c] = 0.f;

    // per-stage: A 128x64 + W 128x64 halves = 2048 16B chunks -> 8/thread
    auto load_stage = [&](int st, int kt) {
        __half* base = dynsmem + st * (BM + BN) * LDS_K;
        __half* Asm = base;
        __half* Wsm = base + BM * LDS_K;
        const int kk = kbase + kt * BK;
#pragma unroll
        for (int j = 0; j < 4; ++j) {
            int t = tid + j * THREADS;     // 0..1023
            int row = t >> 3;              // 0..127
            int cx = t & 7;
            cp_async16(Asm + row * LDS_K + cx * 8,
                       g_x + (size_t)(m0 + row) * GK + kk + cx * 8);
            cp_async16(Wsm + row * LDS_K + cx * 8,
                       g_w + (size_t)(n0 + row) * GK + kk + cx * 8);
        }
    };

    load_stage(0, 0);
    asm volatile("cp.async.commit_group;\n" ::: "memory");
    load_stage(1, 1);
    asm volatile("cp.async.commit_group;\n" ::: "memory");

    const int arow = lane & 15;
    const int acol = (lane >> 4) * 8;

    for (int kt = 0; kt < NK; ++kt) {
        const int st = kt % STAGES;
        asm volatile("cp.async.wait_group 1;\n" ::: "memory");
        __syncthreads();   // stage st ready; all warps past compute of kt-1

        // issue load for kt+2 into buffer (kt+2)%STAGES (= kt-1's buffer, now free)
        if (kt + 2 < NK) load_stage((kt + 2) % STAGES, kt + 2);
        asm volatile("cp.async.commit_group;\n" ::: "memory");

        __half* base = dynsmem + st * (BM + BN) * LDS_K;
        __half* Asm = base;
        __half* Wsm = base + BM * LDS_K;

#pragma unroll
        for (int ks = 0; ks < BK / 16; ++ks) {
            unsigned int afr[4][4];
            unsigned int bfr[4][2];
#pragma unroll
            for (int mi = 0; mi < 4; ++mi) {
                unsigned int addr = smem_u32(
                    Asm + (wm * 64 + mi * 16 + arow) * LDS_K + ks * 16 + acol);
                asm volatile(
                    "ldmatrix.sync.aligned.m8n8.x4.shared.b16 {%0,%1,%2,%3}, [%4];\n"
                    : "=r"(afr[mi][0]), "=r"(afr[mi][1]), "=r"(afr[mi][2]),
                      "=r"(afr[mi][3])
                    : "r"(addr));
            }
#pragma unroll
            for (int nj = 0; nj < 2; ++nj) {
                unsigned int q0, q1, q2, q3;
                unsigned int addr = smem_u32(
                    Wsm + (wn * 32 + nj * 16 + arow) * LDS_K + ks * 16 + acol);
                asm volatile(
                    "ldmatrix.sync.aligned.m8n8.x4.shared.b16 {%0,%1,%2,%3}, [%4];\n"
                    : "=r"(q0), "=r"(q1), "=r"(q2), "=r"(q3)
                    : "r"(addr));
                bfr[nj * 2][0] = q0;
                bfr[nj * 2][1] = q2;
                bfr[nj * 2 + 1][0] = q1;
                bfr[nj * 2 + 1][1] = q3;
            }
#pragma unroll
            for (int mi = 0; mi < 4; ++mi)
#pragma unroll
                for (int nf = 0; nf < 4; ++nf) {
                    asm volatile(
                        "mma.sync.aligned.m16n8k16.row.col.f32.f16.f16.f32 "
                        "{%0,%1,%2,%3}, {%4,%5,%6,%7}, {%8,%9}, {%0,%1,%2,%3};\n"
                        : "+f"(acc[mi][nf][0]), "+f"(acc[mi][nf][1]),
                          "+f"(acc[mi][nf][2]), "+f"(acc[mi][nf][3])
                        : "r"(afr[mi][0]), "r"(afr[mi][1]), "r"(afr[mi][2]),
                          "r"(afr[mi][3]), "r"(bfr[nf][0]), "r"(bfr[nf][1]));
                }
        }
    }

    // epilogue: atomicAdd(out, scale*acc); out pre-initialized with bias*scale
    const int row = lane >> 2;
    const int col2 = (lane & 3) * 2;
#pragma unroll
    for (int mi = 0; mi < 4; ++mi) {
        int m = m0 + wm * 64 + mi * 16 + row;
#pragma unroll
        for (int nf = 0; nf < 4; ++nf) {
            int nn = n0 + wn * 32 + nf * 8 + col2;
            float s0 = scale[nn], s1 = scale[nn + 1];
            atomicAdd(&out[(size_t)m * GN + nn],           acc[mi][nf][0] * s0);
            atomicAdd(&out[(size_t)m * GN + nn + 1],       acc[mi][nf][1] * s1);
            atomicAdd(&out[(size_t)(m + 8) * GN + nn],     acc[mi][nf][2] * s0);
            atomicAdd(&out[(size_t)(m + 8) * GN + nn + 1], acc[mi][nf][3] * s1);
        }
    }
}

// ---------------------------------------------------------------------------
extern "C" void kernel_launch(void* const* d_in, const int* in_sizes, int n_in,
                              void* d_out, int out_size) {
    const float* x      = (const float*)d_in[0];
    const int*   stored = (const int*)d_in[1];
    const int*   sign   = (const int*)d_in[2];
    const float* lmin   = (const float*)d_in[3];
    const float* lmax   = (const float*)d_in[4];
    const float* scale  = (const float*)d_in[5];
    const float* bias   = (const float*)d_in[6];
    float* out = (float*)d_out;

    cudaFuncSetAttribute(k_gemm, cudaFuncAttributeMaxDynamicSharedMemorySize, SMEM_DYN);

    k_decompress<<<2960, 256>>>(stored, sign, lmin, lmax);
    k_convert_x<<<512, 256>>>(x);
    k_init_out<<<1024, 256>>>(bias, scale, out);
    dim3 grid(GN / BN, GM / BM, KSPLIT);   // (86, 4, 2)
    k_gemm<<<grid, THREADS, SMEM_DYN>>>(scale, out);
}